// round 10
// baseline (speedup 1.0000x reference)
#include <cuda_runtime.h>
#include <cuda_bf16.h>

// SparseDualFlow: reference = 100-iter Nesterov proximal loop per element.
// Algebraic collapse (proved R0-R1): the recurrence
//   next_acc  = 0.882*acc + 0.02*flow - 0.01*d
//   next_flow = relu(0.98*flow - 0.882*acc + 0.01*d)
// is linear per element; relu never clips for d>0 (min flow_t = 0.01*d at
// t=1), flow==0 forever for d<=0, and the global convergence flag cannot
// fire before iter ~133 > 100. => flow_100 = K * max(d, 0), K from running
// the exact recurrence once with d=1 (host-side, double).
//
// CONVERGED (R10 = verbatim resubmit of R8 winner; R9 died to broker infra,
// a failure mode proven uncorrelated with kernel content). Evidence:
//  - traffic irreducible: 64MiB in + 64MiB out; 18.05us => 7.43 TB/s
//    apparent = 93% of 8TB/s HBM spec.
//  - BATCH scan 1/4/8/16 -> 19.2/18.66/18.18/18.08us kernel: saturated; B8
//    best end-to-end (dur 20.96us, reproduced 21.2us).
//  - occupancy 81%/49%/20% all ~18.1us: in-flight-bytes-limited.
//  - grid 16384/4096/2048/1024 identical within 1%.
//  - dur - kernel ~= 2.9us = harness graph-replay overhead (single launch).

#define BATCH 8

__global__ void sparse_dual_flow_kernel(const float4* __restrict__ in,
                                        float4* __restrict__ out,
                                        float K, int n4) {
    int base = blockIdx.x * (blockDim.x * BATCH) + threadIdx.x;

    if (base + (BATCH - 1) * blockDim.x < n4) {   // fast path (always, n = 2^24)
        float4 v[BATCH];
        #pragma unroll
        for (int k = 0; k < BATCH; ++k)
            v[k] = __ldcs(&in[base + k * blockDim.x]);   // front-batched loads
        #pragma unroll
        for (int k = 0; k < BATCH; ++k) {
            float4 r;
            r.x = fmaxf(K * v[k].x, 0.0f);
            r.y = fmaxf(K * v[k].y, 0.0f);
            r.z = fmaxf(K * v[k].z, 0.0f);
            r.w = fmaxf(K * v[k].w, 0.0f);
            __stcs(&out[base + k * blockDim.x], r);
        }
    } else {
        #pragma unroll
        for (int k = 0; k < BATCH; ++k) {
            int i = base + k * blockDim.x;
            if (i < n4) {
                float4 d = __ldcs(&in[i]);
                float4 r;
                r.x = fmaxf(K * d.x, 0.0f);
                r.y = fmaxf(K * d.y, 0.0f);
                r.z = fmaxf(K * d.z, 0.0f);
                r.w = fmaxf(K * d.w, 0.0f);
                __stcs(&out[i], r);
            }
        }
    }
}

__global__ void sparse_dual_flow_tail(const float* __restrict__ in,
                                      float* __restrict__ out,
                                      float K, int start, int n) {
    int i = start + blockIdx.x * blockDim.x + threadIdx.x;
    if (i < n) out[i] = fmaxf(K * in[i], 0.0f);
}

static float compute_K() {
    // Exact reference recurrence (reference op order) in double with d = 1.
    const double STEP_SIZE = 0.01, MOMENTUM = 0.9;
    double flow = 0.0, acc = 0.0;
    for (int t = 0; t < 100; ++t) {
        double acc_m = MOMENTUM * acc;
        double gradient = 2.0 * (flow - acc_m) - 1.0;  // d = 1
        double next_acc = acc_m + STEP_SIZE * gradient;
        double next_flow = flow - next_acc;
        if (next_flow < 0.0) next_flow = 0.0;
        flow = next_flow;
        acc = next_acc;
    }
    return (float)flow;
}

extern "C" void kernel_launch(void* const* d_in, const int* in_sizes, int n_in,
                              void* d_out, int out_size) {
    const float* dual = (const float*)d_in[0];
    float* out = (float*)d_out;
    int n = in_sizes[0];

    float K = compute_K();  // host-side, baked as kernel arg at capture time

    int n4 = n / 4;
    if (n4 > 0) {
        const int threads = 256;
        int tile = threads * BATCH;
        int blocks = (n4 + tile - 1) / tile;
        sparse_dual_flow_kernel<<<blocks, threads>>>(
            (const float4*)dual, (float4*)out, K, n4);
    }
    int rem = n - n4 * 4;
    if (rem > 0) {
        sparse_dual_flow_tail<<<1, 64>>>(dual, out, K, n4 * 4, n);
    }
}